// round 7
// baseline (speedup 1.0000x reference)
#include <cuda_runtime.h>
#include <cstdint>

// Problem constants
#define BB 4
#define SS 2048
#define DD 1024
#define HH 16
#define HSZ 64
#define BHH (BB*HH)       // 64
#define MROWS (BB*SS)     // 8192

// ---------------- scratch (static device globals; no allocation) -------------
__device__ float g_Qh[(size_t)BHH * SS * HSZ];   // [b,h,s,hs]
__device__ float g_Kh[(size_t)BHH * SS * HSZ];
__device__ float g_Vh[(size_t)BHH * SS * HSZ];
__device__ float g_ctx[(size_t)MROWS * DD];      // [b,s,d]

// =============================================================================
// tf32 helpers
// =============================================================================
__device__ __forceinline__ uint32_t f2tf(float a) {
    uint32_t r;
    asm("cvt.rna.tf32.f32 %0, %1;" : "=r"(r) : "f"(a));
    return r;
}

__device__ __forceinline__ void mma8(float* c,
                                     uint32_t a0, uint32_t a1, uint32_t a2, uint32_t a3,
                                     uint32_t b0, uint32_t b1)
{
    asm volatile(
        "mma.sync.aligned.m16n8k8.row.col.f32.tf32.tf32.f32 "
        "{%0,%1,%2,%3}, {%4,%5,%6,%7}, {%8,%9}, {%0,%1,%2,%3};\n"
        : "+f"(c[0]), "+f"(c[1]), "+f"(c[2]), "+f"(c[3])
        : "r"(a0), "r"(a1), "r"(a2), "r"(a3), "r"(b0), "r"(b1));
}

// =============================================================================
// 3xTF32 GEMM: C = A[M,K] * W[N,K]^T, M=8192, N=K=1024.
// 128x128 block tile, BK=16, 256 threads (8 warps, 2x4), warp tile 64x32.
// smem stores (hi,lo) tf32 pairs interleaved (uint2), k-transposed.
// HEAD_OUT: scatter into [b,h,s,hs]. Else row-major + bias.
// =============================================================================
#define SPITCH 129           // uint2 pitch per k-row (128 + 1 pad)
#define SBUF  (16 * SPITCH)  // uint2 per matrix per stage

template<bool HEAD_OUT>
__global__ __launch_bounds__(256)
void gemm_tf32(const float* __restrict__ A, const float* __restrict__ W,
               const float* __restrict__ bias, float* __restrict__ C)
{
    extern __shared__ uint2 sm2[];
    // stage p: A at sm2 + p*2*SBUF, W at sm2 + p*2*SBUF + SBUF

    const int tid  = threadIdx.x;
    const int lane = tid & 31;
    const int warp = tid >> 5;
    const int wm   = warp >> 2;      // 0..1
    const int wn   = warp & 3;       // 0..3
    const int g    = lane >> 2;      // 0..7
    const int q    = lane & 3;       // 0..3
    const int rowBase = blockIdx.y * 128;
    const int colBase = blockIdx.x * 128;

    const int lr = tid >> 2;         // 0..63 load row
    const int lc = (tid & 3) << 2;   // 0,4,8,12 load col (k)

    const float* Ap = A + (size_t)(rowBase + lr) * DD + lc;
    const float* Wp = W + (size_t)(colBase + lr) * DD + lc;

    float acc[4][4][4];
#pragma unroll
    for (int mt = 0; mt < 4; mt++)
#pragma unroll
        for (int nt = 0; nt < 4; nt++)
#pragma unroll
            for (int e = 0; e < 4; e++) acc[mt][nt][e] = 0.f;

    // initial global fetch (kt = 0)
    float4 fa0 = *(const float4*)(Ap);
    float4 fa1 = *(const float4*)(Ap + 64 * DD);
    float4 fw0 = *(const float4*)(Wp);
    float4 fw1 = *(const float4*)(Wp + 64 * DD);

    // ---- stage kt=0 into buffer 0 ----
    {
        uint2* dA = sm2;
        uint2* dW = sm2 + SBUF;
        float va0[4] = {fa0.x, fa0.y, fa0.z, fa0.w};
        float va1[4] = {fa1.x, fa1.y, fa1.z, fa1.w};
        float vw0[4] = {fw0.x, fw0.y, fw0.z, fw0.w};
        float vw1[4] = {fw1.x, fw1.y, fw1.z, fw1.w};
#pragma unroll
        for (int i = 0; i < 4; i++) {
            uint32_t h, l;
            h = f2tf(va0[i]); l = f2tf(va0[i] - __uint_as_float(h));
            dA[(lc + i) * SPITCH + lr] = make_uint2(h, l);
            h = f2tf(va1[i]); l = f2tf(va1[i] - __uint_as_float(h));
            dA[(lc + i) * SPITCH + lr + 64] = make_uint2(h, l);
            h = f2tf(vw0[i]); l = f2tf(vw0[i] - __uint_as_float(h));
            dW[(lc + i) * SPITCH + lr] = make_uint2(h, l);
            h = f2tf(vw1[i]); l = f2tf(vw1[i] - __uint_as_float(h));
            dW[(lc + i) * SPITCH + lr + 64] = make_uint2(h, l);
        }
    }
    __syncthreads();

    int p = 0;
    for (int kt = 0; kt < DD / 16; kt++) {
        // prefetch next tile into regs
        if (kt < DD / 16 - 1) {
            const int ko = (kt + 1) * 16;
            fa0 = *(const float4*)(Ap + ko);
            fa1 = *(const float4*)(Ap + ko + 64 * DD);
            fw0 = *(const float4*)(Wp + ko);
            fw1 = *(const float4*)(Wp + ko + 64 * DD);
        }

        // ---- compute on buffer p ----
        {
            const uint2* bA = sm2 + p * (2 * SBUF);
            const uint2* bW = bA + SBUF;
#pragma unroll
            for (int s = 0; s < 2; s++) {
                const int k0 = s * 8 + q;
                const int k1 = k0 + 4;

                // B fragments (hi & lo)
                uint32_t bh[4][2], bl[4][2];
#pragma unroll
                for (int nt = 0; nt < 4; nt++) {
                    const int n0 = wn * 32 + nt * 8 + g;
                    uint2 t0 = bW[k0 * SPITCH + n0];
                    uint2 t1 = bW[k1 * SPITCH + n0];
                    bh[nt][0] = t0.x; bl[nt][0] = t0.y;
                    bh[nt][1] = t1.x; bl[nt][1] = t1.y;
                }
#pragma unroll
                for (int mt = 0; mt < 4; mt++) {
                    const int m0 = wm * 64 + mt * 16 + g;
                    uint2 ta0 = bA[k0 * SPITCH + m0];
                    uint2 ta1 = bA[k0 * SPITCH + m0 + 8];
                    uint2 ta2 = bA[k1 * SPITCH + m0];
                    uint2 ta3 = bA[k1 * SPITCH + m0 + 8];
#pragma unroll
                    for (int nt = 0; nt < 4; nt++) {
                        // hi*hi + hi*lo + lo*hi  (3xTF32)
                        mma8(acc[mt][nt], ta0.x, ta1.x, ta2.x, ta3.x, bh[nt][0], bh[nt][1]);
                        mma8(acc[mt][nt], ta0.x, ta1.x, ta2.x, ta3.x, bl[nt][0], bl[nt][1]);
                        mma8(acc[mt][nt], ta0.y, ta1.y, ta2.y, ta3.y, bh[nt][0], bh[nt][1]);
                    }
                }
            }
        }

        // ---- store prefetched tile into buffer 1-p ----
        if (kt < DD / 16 - 1) {
            uint2* dA = sm2 + (1 - p) * (2 * SBUF);
            uint2* dW = dA + SBUF;
            float va0[4] = {fa0.x, fa0.y, fa0.z, fa0.w};
            float va1[4] = {fa1.x, fa1.y, fa1.z, fa1.w};
            float vw0[4] = {fw0.x, fw0.y, fw0.z, fw0.w};
            float vw1[4] = {fw1.x, fw1.y, fw1.z, fw1.w};
#pragma unroll
            for (int i = 0; i < 4; i++) {
                uint32_t h, l;
                h = f2tf(va0[i]); l = f2tf(va0[i] - __uint_as_float(h));
                dA[(lc + i) * SPITCH + lr] = make_uint2(h, l);
                h = f2tf(va1[i]); l = f2tf(va1[i] - __uint_as_float(h));
                dA[(lc + i) * SPITCH + lr + 64] = make_uint2(h, l);
                h = f2tf(vw0[i]); l = f2tf(vw0[i] - __uint_as_float(h));
                dW[(lc + i) * SPITCH + lr] = make_uint2(h, l);
                h = f2tf(vw1[i]); l = f2tf(vw1[i] - __uint_as_float(h));
                dW[(lc + i) * SPITCH + lr + 64] = make_uint2(h, l);
            }
            __syncthreads();
            p ^= 1;
        }
    }

    // ------------------------- epilogue -------------------------
#pragma unroll
    for (int mt = 0; mt < 4; mt++) {
        const int mBase = rowBase + wm * 64 + mt * 16 + g;
#pragma unroll
        for (int nt = 0; nt < 4; nt++) {
            const int n = colBase + wn * 32 + nt * 8 + 2 * q;
#pragma unroll
            for (int rr = 0; rr < 2; rr++) {
                const int m = mBase + rr * 8;
                const float c0 = acc[mt][nt][rr * 2 + 0];
                const float c1 = acc[mt][nt][rr * 2 + 1];
                if (HEAD_OUT) {
                    const int b  = m >> 11;
                    const int s  = m & (SS - 1);
                    const int h  = n >> 6;
                    const int hs = n & 63;
                    float2 v; v.x = c0; v.y = c1;
                    *(float2*)&C[(((size_t)(b * HH + h)) * SS + s) * HSZ + hs] = v;
                } else {
                    float2 bv = *(const float2*)&bias[n];
                    float2 v; v.x = c0 + bv.x; v.y = c1 + bv.y;
                    *(float2*)&C[(size_t)m * DD + n] = v;
                }
            }
        }
    }
}

// =============================================================================
// Causal flash attention, fp32 (unchanged — known good, 2870us baseline part).
// =============================================================================
#define FLD 68   // padded leading dim (float4-aligned)

__global__ __launch_bounds__(256, 2)
void flash_kernel(const float* __restrict__ Q, const float* __restrict__ K,
                  const float* __restrict__ V, float* __restrict__ ctx)
{
    extern __shared__ float sm[];
    float* Qs = sm;                 // [hs][i]  (transposed)
    float* Ks = sm + 64 * FLD;      // [hs][j]  (transposed)
    float* Vs = sm + 2 * 64 * FLD;  // [j][d]   (natural)
    float* Ps = sm + 3 * 64 * FLD;  // [j][i]   (transposed)

    const int tid = threadIdx.x;
    const int ty  = tid >> 4;
    const int tx  = tid & 15;
    const int i0  = ty * 4;
    const int j0  = tx * 4;
    const int qt  = blockIdx.x;
    const int bh  = blockIdx.y;

    const float* Qbase = Q + ((size_t)bh * SS + qt * 64) * HSZ;
    for (int idx = tid; idx < 64 * 64; idx += 256) {
        const int r = idx >> 6, c = idx & 63;
        Qs[c * FLD + r] = Qbase[r * HSZ + c];
    }

    float acc[4][4];
    float mrow[4], lrow[4];
#pragma unroll
    for (int r = 0; r < 4; r++) {
        mrow[r] = -1e30f; lrow[r] = 0.f;
#pragma unroll
        for (int c = 0; c < 4; c++) acc[r][c] = 0.f;
    }

    for (int kt = 0; kt <= qt; kt++) {
        const float* Kb = K + ((size_t)bh * SS + kt * 64) * HSZ;
        const float* Vb = V + ((size_t)bh * SS + kt * 64) * HSZ;

        __syncthreads();
        for (int idx = tid; idx < 64 * 64; idx += 256) {
            const int r = idx >> 6, c = idx & 63;
            Ks[c * FLD + r] = Kb[r * HSZ + c];
            Vs[r * FLD + c] = Vb[r * HSZ + c];
        }
        __syncthreads();

        float s[4][4];
#pragma unroll
        for (int r = 0; r < 4; r++)
#pragma unroll
            for (int c = 0; c < 4; c++) s[r][c] = 0.f;

#pragma unroll
        for (int k = 0; k < 64; k++) {
            float4 qv = *(const float4*)&Qs[k * FLD + i0];
            float4 kv = *(const float4*)&Ks[k * FLD + j0];
            float qa[4] = {qv.x, qv.y, qv.z, qv.w};
            float ka[4] = {kv.x, kv.y, kv.z, kv.w};
#pragma unroll
            for (int r = 0; r < 4; r++)
#pragma unroll
                for (int c = 0; c < 4; c++)
                    s[r][c] = fmaf(qa[r], ka[c], s[r][c]);
        }

        const int qg0 = qt * 64 + i0;
        const int kg0 = kt * 64 + j0;
#pragma unroll
        for (int r = 0; r < 4; r++)
#pragma unroll
            for (int c = 0; c < 4; c++) {
                float v = s[r][c] * 0.125f;
                if (kg0 + c > qg0 + r) v = -1e30f;
                s[r][c] = v;
            }

#pragma unroll
        for (int r = 0; r < 4; r++) {
            float rm = fmaxf(fmaxf(s[r][0], s[r][1]), fmaxf(s[r][2], s[r][3]));
#pragma unroll
            for (int d = 1; d < 16; d <<= 1)
                rm = fmaxf(rm, __shfl_xor_sync(0xffffffffu, rm, d));
            const float mnew = fmaxf(mrow[r], rm);
            const float corr = __expf(mrow[r] - mnew);
            mrow[r] = mnew;
            float rs = 0.f;
#pragma unroll
            for (int c = 0; c < 4; c++) {
                const float pv = __expf(s[r][c] - mnew);
                s[r][c] = pv;
                rs += pv;
            }
#pragma unroll
            for (int d = 1; d < 16; d <<= 1)
                rs += __shfl_xor_sync(0xffffffffu, rs, d);
            lrow[r] = lrow[r] * corr + rs;
#pragma unroll
            for (int c = 0; c < 4; c++) acc[r][c] *= corr;
        }

#pragma unroll
        for (int c = 0; c < 4; c++) {
            float4 pv;
            pv.x = s[0][c]; pv.y = s[1][c]; pv.z = s[2][c]; pv.w = s[3][c];
            *(float4*)&Ps[(j0 + c) * FLD + i0] = pv;
        }
        __syncthreads();

#pragma unroll
        for (int j = 0; j < 64; j++) {
            float4 pv = *(const float4*)&Ps[j * FLD + i0];
            float4 vv = *(const float4*)&Vs[j * FLD + j0];
            float pa[4] = {pv.x, pv.y, pv.z, pv.w};
            float va[4] = {vv.x, vv.y, vv.z, vv.w};
#pragma unroll
            for (int r = 0; r < 4; r++)
#pragma unroll
                for (int c = 0; c < 4; c++)
                    acc[r][c] = fmaf(pa[r], va[c], acc[r][c]);
        }
    }

    const int b = bh >> 4, h = bh & 15;
#pragma unroll
    for (int r = 0; r < 4; r++) {
        const int qg = qt * 64 + i0 + r;
        const float inv = 1.f / lrow[r];
        float4 o;
        o.x = acc[r][0] * inv; o.y = acc[r][1] * inv;
        o.z = acc[r][2] * inv; o.w = acc[r][3] * inv;
        *(float4*)&ctx[((size_t)(b * SS + qg)) * DD + h * HSZ + j0] = o;
    }
}

// =============================================================================
// launch
// =============================================================================
extern "C" void kernel_launch(void* const* d_in, const int* in_sizes, int n_in,
                              void* d_out, int out_size)
{
    const float* x  = (const float*)d_in[0];
    const float* Wk = (const float*)d_in[1];
    const float* Wq = (const float*)d_in[2];
    const float* Wv = (const float*)d_in[3];
    const float* Wo = (const float*)d_in[4];
    const float* bo = (const float*)d_in[5];
    float* out = (float*)d_out;

    float *Qh, *Kh, *Vh, *ctx;
    cudaGetSymbolAddress((void**)&Qh,  g_Qh);
    cudaGetSymbolAddress((void**)&Kh,  g_Kh);
    cudaGetSymbolAddress((void**)&Vh,  g_Vh);
    cudaGetSymbolAddress((void**)&ctx, g_ctx);

    const int gemmSmem  = 4 * SBUF * (int)sizeof(uint2);     // 66048 B
    const int flashSmem = 4 * 64 * FLD * (int)sizeof(float); // 69632 B

    // Idempotent attribute setup every call (cheap host-side; no static guards).
    cudaFuncSetAttribute(gemm_tf32<true>,
                         cudaFuncAttributeMaxDynamicSharedMemorySize, gemmSmem);
    cudaFuncSetAttribute(gemm_tf32<false>,
                         cudaFuncAttributeMaxDynamicSharedMemorySize, gemmSmem);
    cudaFuncSetAttribute(flash_kernel,
                         cudaFuncAttributeMaxDynamicSharedMemorySize, flashSmem);

    const dim3 gGemm(DD / 128, MROWS / 128);   // (8, 64)
    gemm_tf32<true><<<gGemm, 256, gemmSmem>>>(x, Wq, nullptr, Qh);
    gemm_tf32<true><<<gGemm, 256, gemmSmem>>>(x, Wk, nullptr, Kh);
    gemm_tf32<true><<<gGemm, 256, gemmSmem>>>(x, Wv, nullptr, Vh);

    const dim3 gFlash(SS / 64, BHH);           // (32, 64)
    flash_kernel<<<gFlash, 256, flashSmem>>>(Qh, Kh, Vh, ctx);

    gemm_tf32<false><<<gGemm, 256, gemmSmem>>>(ctx, Wo, bo, out);
}

// round 9
// speedup vs baseline: 1.9872x; 1.9872x over previous
#include <cuda_runtime.h>
#include <cuda_bf16.h>
#include <cstdint>

// Problem constants
#define BB 4
#define SS 2048
#define DD 1024
#define HH 16
#define HSZ 64
#define BHH (BB*HH)       // 64
#define MROWS (BB*SS)     // 8192
#define GK DD             // 1024

// ---------------- scratch (static device globals; no allocation) -------------
__device__ float g_Qh[(size_t)BHH * SS * HSZ];     // [b,h,s,hs]
__device__ float g_Kh[(size_t)BHH * SS * HSZ];
__device__ float g_Vh[(size_t)BHH * SS * HSZ];
__device__ float g_ctx[(size_t)MROWS * DD];        // [b,s,d]
__device__ __nv_bfloat16 g_xhi[(size_t)MROWS * DD];
__device__ __nv_bfloat16 g_xlo[(size_t)MROWS * DD];
__device__ __nv_bfloat16 g_chi[(size_t)MROWS * DD];
__device__ __nv_bfloat16 g_clo[(size_t)MROWS * DD];
__device__ __nv_bfloat16 g_Whi[4][(size_t)DD * DD];
__device__ __nv_bfloat16 g_Wlo[4][(size_t)DD * DD];

// =============================================================================
// helpers (arch-neutral: mma.sync / ldmatrix / cp.async only — NO tcgen05)
// =============================================================================
__device__ __forceinline__ uint32_t smem_u32(const void* p) {
    uint32_t a;
    asm("{ .reg .u64 t; cvta.to.shared.u64 t, %1; cvt.u32.u64 %0, t; }"
        : "=r"(a) : "l"(p));
    return a;
}

__device__ __forceinline__ void cp16(uint32_t dst, const void* src) {
    asm volatile("cp.async.cg.shared.global [%0], [%1], 16;"
                 :: "r"(dst), "l"(src) : "memory");
}
__device__ __forceinline__ void cp_commit() {
    asm volatile("cp.async.commit_group;" ::: "memory");
}
template<int N>
__device__ __forceinline__ void cp_wait() {
    asm volatile("cp.async.wait_group %0;" :: "n"(N) : "memory");
}

__device__ __forceinline__ void ldsm4(uint32_t& r0, uint32_t& r1,
                                      uint32_t& r2, uint32_t& r3, uint32_t a) {
    asm volatile("ldmatrix.sync.aligned.m8n8.x4.shared.b16 {%0,%1,%2,%3}, [%4];"
                 : "=r"(r0), "=r"(r1), "=r"(r2), "=r"(r3) : "r"(a));
}

__device__ __forceinline__ void mma16816(float* c,
                                         uint32_t a0, uint32_t a1, uint32_t a2, uint32_t a3,
                                         uint32_t b0, uint32_t b1) {
    asm volatile(
        "mma.sync.aligned.m16n8k16.row.col.f32.bf16.bf16.f32 "
        "{%0,%1,%2,%3}, {%4,%5,%6,%7}, {%8,%9}, {%0,%1,%2,%3};"
        : "+f"(c[0]), "+f"(c[1]), "+f"(c[2]), "+f"(c[3])
        : "r"(a0), "r"(a1), "r"(a2), "r"(a3), "r"(b0), "r"(b1));
}

// =============================================================================
// fp32 -> bf16 (hi, lo) split conversion
// =============================================================================
__global__ void convert_hilo(const float* __restrict__ s,
                             __nv_bfloat16* __restrict__ hi,
                             __nv_bfloat16* __restrict__ lo, int n)
{
    const int i = (blockIdx.x * blockDim.x + threadIdx.x) << 2;
    if (i >= n) return;
    float4 v = *(const float4*)(s + i);
    float f[4] = {v.x, v.y, v.z, v.w};
    __nv_bfloat16 h[4], l[4];
#pragma unroll
    for (int j = 0; j < 4; j++) {
        h[j] = __float2bfloat16_rn(f[j]);
        l[j] = __float2bfloat16_rn(f[j] - __bfloat162float(h[j]));
    }
    __nv_bfloat162* ph = (__nv_bfloat162*)(hi + i);
    __nv_bfloat162* pl = (__nv_bfloat162*)(lo + i);
    ph[0] = __nv_bfloat162{h[0], h[1]};
    ph[1] = __nv_bfloat162{h[2], h[3]};
    pl[0] = __nv_bfloat162{l[0], l[1]};
    pl[1] = __nv_bfloat162{l[2], l[3]};
}

// =============================================================================
// bf16 3-term mma.sync GEMM: C[8192,1024] = A[M,K]*W[N,K]^T  (fp32-split ops)
// 128x128 CTA tile, BK=32, 256 threads (8 warps 2x4, warp tile 64x32),
// cp.async double buffer, ldmatrix fragments, fp32 accum.
// MODE 0: scatter into [b,h,s,hs].  MODE 1: row-major + bias.
// =============================================================================
#define BKC 32                 // k elements per stage
#define AROWB 80               // smem row: 32 bf16 = 64B + 16B pad (LDSM conflict-free)
#define TILEB (128 * AROWB)    // 10240 B per tile
#define STAGEB (4 * TILEB)     // Ahi,Alo,Bhi,Blo
#define GEMM_SMEM (2 * STAGEB) // 81920 B

template<int MODE>
__global__ __launch_bounds__(256, 1)
void gemm_bf16(const __nv_bfloat16* __restrict__ Ahi, const __nv_bfloat16* __restrict__ Alo,
               const __nv_bfloat16* __restrict__ Bhi, const __nv_bfloat16* __restrict__ Blo,
               const float* __restrict__ bias, float* __restrict__ C)
{
    extern __shared__ char smem[];
    const uint32_t smem_base = smem_u32(smem);
    const int tid  = threadIdx.x;
    const int lane = tid & 31;
    const int warp = tid >> 5;
    const int wm   = warp >> 2;          // 0..1
    const int wn   = warp & 3;           // 0..3
    const int rowBase = blockIdx.y * 128;
    const int colBase = blockIdx.x * 128;

    const __nv_bfloat16* srcs[4] = {
        Ahi + (size_t)rowBase * GK, Alo + (size_t)rowBase * GK,
        Bhi + (size_t)colBase * GK, Blo + (size_t)colBase * GK };

    // per-lane ldmatrix address offsets (bytes)
    const uint32_t aOff = (lane & 15) * AROWB + (lane >> 4) * 16;
    const uint32_t bOff = ((lane & 7) + ((lane >> 4) << 3)) * AROWB
                        + ((lane >> 3) & 1) * 16;

    float acc[4][4][4];
#pragma unroll
    for (int mt = 0; mt < 4; mt++)
#pragma unroll
        for (int nt = 0; nt < 4; nt++)
#pragma unroll
            for (int e = 0; e < 4; e++) acc[mt][nt][e] = 0.f;

    // stage loader: 4 tiles x 128 rows x 32 bf16 (64B) -> 2048 x 16B chunks
    auto load_stage = [&](int kc, int stg) {
        const int kbase = kc * BKC;
        const uint32_t sbase = smem_base + stg * STAGEB;
#pragma unroll
        for (int i = 0; i < 8; i++) {
            const int task = tid + i * 256;       // 0..2047
            const int tile = task >> 9;
            const int rem  = task & 511;
            const int r    = rem >> 2;
            const int ch   = rem & 3;
            const void* src = srcs[tile] + (size_t)r * GK + kbase + ch * 8;
            cp16(sbase + tile * TILEB + r * AROWB + ch * 16, src);
        }
    };

    // compute one stage (two k16 steps)
    auto compute_stage = [&](int stg) {
        const uint32_t sb  = smem_base + stg * STAGEB;
        const uint32_t sAh = sb;
        const uint32_t sAl = sb + TILEB;
        const uint32_t sBh = sb + 2 * TILEB;
        const uint32_t sBl = sb + 3 * TILEB;
#pragma unroll
        for (int ks = 0; ks < 2; ks++) {
            const uint32_t kb = ks * 32;          // 16 bf16 = 32 bytes
            uint32_t ah[4][4], al[4][4];
#pragma unroll
            for (int mt = 0; mt < 4; mt++) {
                const uint32_t ro = (wm * 64 + mt * 16) * AROWB + kb;
                ldsm4(ah[mt][0], ah[mt][1], ah[mt][2], ah[mt][3], sAh + ro + aOff);
                ldsm4(al[mt][0], al[mt][1], al[mt][2], al[mt][3], sAl + ro + aOff);
            }
            uint32_t bh[4][2], bl[4][2];
#pragma unroll
            for (int np = 0; np < 2; np++) {      // each x4 covers 2 n-tiles
                const uint32_t ro = (wn * 32 + np * 16) * AROWB + kb;
                ldsm4(bh[2*np][0], bh[2*np][1], bh[2*np+1][0], bh[2*np+1][1], sBh + ro + bOff);
                ldsm4(bl[2*np][0], bl[2*np][1], bl[2*np+1][0], bl[2*np+1][1], sBl + ro + bOff);
            }
#pragma unroll
            for (int mt = 0; mt < 4; mt++)
#pragma unroll
                for (int nt = 0; nt < 4; nt++) {
                    mma16816(acc[mt][nt], ah[mt][0], ah[mt][1], ah[mt][2], ah[mt][3],
                             bh[nt][0], bh[nt][1]);
                    mma16816(acc[mt][nt], ah[mt][0], ah[mt][1], ah[mt][2], ah[mt][3],
                             bl[nt][0], bl[nt][1]);
                    mma16816(acc[mt][nt], al[mt][0], al[mt][1], al[mt][2], al[mt][3],
                             bh[nt][0], bh[nt][1]);
                }
        }
    };

    const int NSTAGES = GK / BKC;                 // 32
    load_stage(0, 0);
    cp_commit();

    for (int kt = 0; kt < NSTAGES; kt++) {
        if (kt + 1 < NSTAGES) {
            load_stage(kt + 1, (kt + 1) & 1);
            cp_commit();
            cp_wait<1>();                         // stage kt ready
        } else {
            cp_wait<0>();
        }
        __syncthreads();
        compute_stage(kt & 1);
        __syncthreads();                          // before overwriting this buffer
    }

    // ------------------------- epilogue -------------------------
    const int g = lane >> 2;                      // 0..7
    const int q = lane & 3;                       // 0..3
#pragma unroll
    for (int mt = 0; mt < 4; mt++) {
        const int mBase = rowBase + wm * 64 + mt * 16 + g;
#pragma unroll
        for (int nt = 0; nt < 4; nt++) {
            const int n = colBase + wn * 32 + nt * 8 + 2 * q;
#pragma unroll
            for (int rr = 0; rr < 2; rr++) {
                const int m = mBase + rr * 8;
                const float c0 = acc[mt][nt][rr * 2 + 0];
                const float c1 = acc[mt][nt][rr * 2 + 1];
                if (MODE == 0) {
                    const int b = m >> 11, s = m & (SS - 1);
                    const int h = n >> 6,  hs = n & 63;
                    float2 v; v.x = c0; v.y = c1;
                    *(float2*)&C[(((size_t)(b * HH + h)) * SS + s) * HSZ + hs] = v;
                } else {
                    float2 bv = *(const float2*)&bias[n];
                    float2 v; v.x = c0 + bv.x; v.y = c1 + bv.y;
                    *(float2*)&C[(size_t)m * DD + n] = v;
                }
            }
        }
    }
}

// =============================================================================
// Causal flash attention, fp32 (unchanged — known good).
// =============================================================================
#define FLD 68

__global__ __launch_bounds__(256, 2)
void flash_kernel(const float* __restrict__ Q, const float* __restrict__ K,
                  const float* __restrict__ V, float* __restrict__ ctx)
{
    extern __shared__ float sm[];
    float* Qs = sm;
    float* Ks = sm + 64 * FLD;
    float* Vs = sm + 2 * 64 * FLD;
    float* Ps = sm + 3 * 64 * FLD;

    const int tid = threadIdx.x;
    const int ty  = tid >> 4;
    const int tx  = tid & 15;
    const int i0  = ty * 4;
    const int j0  = tx * 4;
    const int qt  = blockIdx.x;
    const int bh  = blockIdx.y;

    const float* Qbase = Q + ((size_t)bh * SS + qt * 64) * HSZ;
    for (int idx = tid; idx < 64 * 64; idx += 256) {
        const int r = idx >> 6, c = idx & 63;
        Qs[c * FLD + r] = Qbase[r * HSZ + c];
    }

    float acc[4][4];
    float mrow[4], lrow[4];
#pragma unroll
    for (int r = 0; r < 4; r++) {
        mrow[r] = -1e30f; lrow[r] = 0.f;
#pragma unroll
        for (int c = 0; c < 4; c++) acc[r][c] = 0.f;
    }

    for (int kt = 0; kt <= qt; kt++) {
        const float* Kb = K + ((size_t)bh * SS + kt * 64) * HSZ;
        const float* Vb = V + ((size_t)bh * SS + kt * 64) * HSZ;

        __syncthreads();
        for (int idx = tid; idx < 64 * 64; idx += 256) {
            const int r = idx >> 6, c = idx & 63;
            Ks[c * FLD + r] = Kb[r * HSZ + c];
            Vs[r * FLD + c] = Vb[r * HSZ + c];
        }
        __syncthreads();

        float s[4][4];
#pragma unroll
        for (int r = 0; r < 4; r++)
#pragma unroll
            for (int c = 0; c < 4; c++) s[r][c] = 0.f;

#pragma unroll
        for (int k = 0; k < 64; k++) {
            float4 qv = *(const float4*)&Qs[k * FLD + i0];
            float4 kv = *(const float4*)&Ks[k * FLD + j0];
            float qa[4] = {qv.x, qv.y, qv.z, qv.w};
            float ka[4] = {kv.x, kv.y, kv.z, kv.w};
#pragma unroll
            for (int r = 0; r < 4; r++)
#pragma unroll
                for (int c = 0; c < 4; c++)
                    s[r][c] = fmaf(qa[r], ka[c], s[r][c]);
        }

        const int qg0 = qt * 64 + i0;
        const int kg0 = kt * 64 + j0;
#pragma unroll
        for (int r = 0; r < 4; r++)
#pragma unroll
            for (int c = 0; c < 4; c++) {
                float v = s[r][c] * 0.125f;
                if (kg0 + c > qg0 + r) v = -1e30f;
                s[r][c] = v;
            }

#pragma unroll
        for (int r = 0; r < 4; r++) {
            float rm = fmaxf(fmaxf(s[r][0], s[r][1]), fmaxf(s[r][2], s[r][3]));
#pragma unroll
            for (int d = 1; d < 16; d <<= 1)
                rm = fmaxf(rm, __shfl_xor_sync(0xffffffffu, rm, d));
            const float mnew = fmaxf(mrow[r], rm);
            const float corr = __expf(mrow[r] - mnew);
            mrow[r] = mnew;
            float rs = 0.f;
#pragma unroll
            for (int c = 0; c < 4; c++) {
                const float pv = __expf(s[r][c] - mnew);
                s[r][c] = pv;
                rs += pv;
            }
#pragma unroll
            for (int d = 1; d < 16; d <<= 1)
                rs += __shfl_xor_sync(0xffffffffu, rs, d);
            lrow[r] = lrow[r] * corr + rs;
#pragma unroll
            for (int c = 0; c < 4; c++) acc[r][c] *= corr;
        }

#pragma unroll
        for (int c = 0; c < 4; c++) {
            float4 pv;
            pv.x = s[0][c]; pv.y = s[1][c]; pv.z = s[2][c]; pv.w = s[3][c];
            *(float4*)&Ps[(j0 + c) * FLD + i0] = pv;
        }
        __syncthreads();

#pragma unroll
        for (int j = 0; j < 64; j++) {
            float4 pv = *(const float4*)&Ps[j * FLD + i0];
            float4 vv = *(const float4*)&Vs[j * FLD + j0];
            float pa[4] = {pv.x, pv.y, pv.z, pv.w};
            float va[4] = {vv.x, vv.y, vv.z, vv.w};
#pragma unroll
            for (int r = 0; r < 4; r++)
#pragma unroll
                for (int c = 0; c < 4; c++)
                    acc[r][c] = fmaf(pa[r], va[c], acc[r][c]);
        }
    }

    const int b = bh >> 4, h = bh & 15;
#pragma unroll
    for (int r = 0; r < 4; r++) {
        const int qg = qt * 64 + i0 + r;
        const float inv = 1.f / lrow[r];
        float4 o;
        o.x = acc[r][0] * inv; o.y = acc[r][1] * inv;
        o.z = acc[r][2] * inv; o.w = acc[r][3] * inv;
        *(float4*)&ctx[((size_t)(b * SS + qg)) * DD + h * HSZ + j0] = o;
    }
}

// =============================================================================
// launch
// =============================================================================
extern "C" void kernel_launch(void* const* d_in, const int* in_sizes, int n_in,
                              void* d_out, int out_size)
{
    const float* x  = (const float*)d_in[0];
    const float* Wk = (const float*)d_in[1];
    const float* Wq = (const float*)d_in[2];
    const float* Wv = (const float*)d_in[3];
    const float* Wo = (const float*)d_in[4];
    const float* bo = (const float*)d_in[5];
    float* out = (float*)d_out;

    float *Qh, *Kh, *Vh, *ctx;
    __nv_bfloat16 *xhi, *xlo, *chi, *clo, *Whi, *Wlo;
    cudaGetSymbolAddress((void**)&Qh,  g_Qh);
    cudaGetSymbolAddress((void**)&Kh,  g_Kh);
    cudaGetSymbolAddress((void**)&Vh,  g_Vh);
    cudaGetSymbolAddress((void**)&ctx, g_ctx);
    cudaGetSymbolAddress((void**)&xhi, g_xhi);
    cudaGetSymbolAddress((void**)&xlo, g_xlo);
    cudaGetSymbolAddress((void**)&chi, g_chi);
    cudaGetSymbolAddress((void**)&clo, g_clo);
    cudaGetSymbolAddress((void**)&Whi, g_Whi);
    cudaGetSymbolAddress((void**)&Wlo, g_Wlo);

    const size_t WSZ = (size_t)DD * DD;
    const int nX = MROWS * DD;
    const int nW = DD * DD;

    const int flashSmem = 4 * 64 * FLD * (int)sizeof(float);
    cudaFuncSetAttribute(gemm_bf16<0>, cudaFuncAttributeMaxDynamicSharedMemorySize, GEMM_SMEM);
    cudaFuncSetAttribute(gemm_bf16<1>, cudaFuncAttributeMaxDynamicSharedMemorySize, GEMM_SMEM);
    cudaFuncSetAttribute(flash_kernel, cudaFuncAttributeMaxDynamicSharedMemorySize, flashSmem);

    // ---- hi/lo conversions ----
    convert_hilo<<<nX / 4 / 256, 256>>>(x,  xhi, xlo, nX);
    convert_hilo<<<nW / 4 / 256, 256>>>(Wq, Whi + 0 * WSZ, Wlo + 0 * WSZ, nW);
    convert_hilo<<<nW / 4 / 256, 256>>>(Wk, Whi + 1 * WSZ, Wlo + 1 * WSZ, nW);
    convert_hilo<<<nW / 4 / 256, 256>>>(Wv, Whi + 2 * WSZ, Wlo + 2 * WSZ, nW);
    convert_hilo<<<nW / 4 / 256, 256>>>(Wo, Whi + 3 * WSZ, Wlo + 3 * WSZ, nW);

    // ---- projections (bf16 3-term mma.sync) ----
    const dim3 gGemm(DD / 128, MROWS / 128);   // (8, 64)
    gemm_bf16<0><<<gGemm, 256, GEMM_SMEM>>>(xhi, xlo, Whi + 0 * WSZ, Wlo + 0 * WSZ, nullptr, Qh);
    gemm_bf16<0><<<gGemm, 256, GEMM_SMEM>>>(xhi, xlo, Whi + 1 * WSZ, Wlo + 1 * WSZ, nullptr, Kh);
    gemm_bf16<0><<<gGemm, 256, GEMM_SMEM>>>(xhi, xlo, Whi + 2 * WSZ, Wlo + 2 * WSZ, nullptr, Vh);

    // ---- attention ----
    const dim3 gFlash(SS / 64, BHH);           // (32, 64)
    flash_kernel<<<gFlash, 256, flashSmem>>>(Qh, Kh, Vh, ctx);

    // ---- output projection ----
    convert_hilo<<<nX / 4 / 256, 256>>>(ctx, chi, clo, nX);
    gemm_bf16<1><<<gGemm, 256, GEMM_SMEM>>>(chi, clo, Whi + 3 * WSZ, Wlo + 3 * WSZ, bo, out);
}

// round 10
// speedup vs baseline: 2.9783x; 1.4987x over previous
#include <cuda_runtime.h>
#include <cuda_bf16.h>
#include <cstdint>

// Problem constants
#define BB 4
#define SS 2048
#define DD 1024
#define HH 16
#define HSZ 64
#define BHH (BB*HH)       // 64
#define MROWS (BB*SS)     // 8192
#define GK DD             // 1024

// ---------------- scratch (static device globals; no allocation) -------------
__device__ float g_Qh[(size_t)BHH * SS * HSZ];     // [b,h,s,hs]
__device__ float g_Kh[(size_t)BHH * SS * HSZ];
__device__ float g_Vh[(size_t)BHH * SS * HSZ];
__device__ __nv_bfloat16 g_xhi[(size_t)MROWS * DD];
__device__ __nv_bfloat16 g_xlo[(size_t)MROWS * DD];
__device__ __nv_bfloat16 g_chi[(size_t)MROWS * DD];
__device__ __nv_bfloat16 g_clo[(size_t)MROWS * DD];
__device__ __nv_bfloat16 g_Whi[4][(size_t)DD * DD];
__device__ __nv_bfloat16 g_Wlo[4][(size_t)DD * DD];

// =============================================================================
// helpers (arch-neutral: mma.sync / ldmatrix / cp.async — NO tcgen05)
// =============================================================================
__device__ __forceinline__ uint32_t smem_u32(const void* p) {
    uint32_t a;
    asm("{ .reg .u64 t; cvta.to.shared.u64 t, %1; cvt.u32.u64 %0, t; }"
        : "=r"(a) : "l"(p));
    return a;
}

__device__ __forceinline__ void cp16(uint32_t dst, const void* src) {
    asm volatile("cp.async.cg.shared.global [%0], [%1], 16;"
                 :: "r"(dst), "l"(src) : "memory");
}
__device__ __forceinline__ void cp_commit() {
    asm volatile("cp.async.commit_group;" ::: "memory");
}
template<int N>
__device__ __forceinline__ void cp_wait() {
    asm volatile("cp.async.wait_group %0;" :: "n"(N) : "memory");
}

__device__ __forceinline__ void ldsm4(uint32_t& r0, uint32_t& r1,
                                      uint32_t& r2, uint32_t& r3, uint32_t a) {
    asm volatile("ldmatrix.sync.aligned.m8n8.x4.shared.b16 {%0,%1,%2,%3}, [%4];"
                 : "=r"(r0), "=r"(r1), "=r"(r2), "=r"(r3) : "r"(a));
}

__device__ __forceinline__ void mma16816(float* c,
                                         uint32_t a0, uint32_t a1, uint32_t a2, uint32_t a3,
                                         uint32_t b0, uint32_t b1) {
    asm volatile(
        "mma.sync.aligned.m16n8k16.row.col.f32.bf16.bf16.f32 "
        "{%0,%1,%2,%3}, {%4,%5,%6,%7}, {%8,%9}, {%0,%1,%2,%3};"
        : "+f"(c[0]), "+f"(c[1]), "+f"(c[2]), "+f"(c[3])
        : "r"(a0), "r"(a1), "r"(a2), "r"(a3), "r"(b0), "r"(b1));
}

// fp32 pair -> packed bf16x2 hi + lo residual
__device__ __forceinline__ void split2(float x, float y, uint32_t& h, uint32_t& l) {
    __nv_bfloat16 h0 = __float2bfloat16_rn(x);
    __nv_bfloat16 h1 = __float2bfloat16_rn(y);
    __nv_bfloat16 l0 = __float2bfloat16_rn(x - __bfloat162float(h0));
    __nv_bfloat16 l1 = __float2bfloat16_rn(y - __bfloat162float(h1));
    __nv_bfloat162 hh{h0, h1}, ll{l0, l1};
    h = *(uint32_t*)&hh;
    l = *(uint32_t*)&ll;
}

// Fast exp on fma/alu pipes (no MUFU). Valid for x <= ~0 (clamped below).
// exp(x) = 2^n * 2^f, n=round(x*log2e), f in [-0.5,0.5], deg-5 Taylor (~2e-6 rel).
__device__ __forceinline__ float fexp(float x) {
    float z = fmaxf(x * 1.442695041f, -126.0f);
    float t = z + 12582912.0f;                     // 1.5*2^23: round to nearest
    float n = t - 12582912.0f;
    float f = z - n;
    int   e = (__float_as_int(t) & 0x7FFFFF) - 0x400000;   // (int)n
    float p = 1.3333558e-3f;
    p = fmaf(p, f, 9.6181291e-3f);
    p = fmaf(p, f, 5.5504109e-2f);
    p = fmaf(p, f, 2.4022651e-1f);
    p = fmaf(p, f, 6.9314718e-1f);
    p = fmaf(p, f, 1.0f);
    return p * __int_as_float((e + 127) << 23);
}

// =============================================================================
// fp32 -> bf16 (hi, lo) split conversion
// =============================================================================
__global__ void convert_hilo(const float* __restrict__ s,
                             __nv_bfloat16* __restrict__ hi,
                             __nv_bfloat16* __restrict__ lo, int n)
{
    const int i = (blockIdx.x * blockDim.x + threadIdx.x) << 2;
    if (i >= n) return;
    float4 v = *(const float4*)(s + i);
    float f[4] = {v.x, v.y, v.z, v.w};
    __nv_bfloat16 h[4], l[4];
#pragma unroll
    for (int j = 0; j < 4; j++) {
        h[j] = __float2bfloat16_rn(f[j]);
        l[j] = __float2bfloat16_rn(f[j] - __bfloat162float(h[j]));
    }
    __nv_bfloat162* ph = (__nv_bfloat162*)(hi + i);
    __nv_bfloat162* pl = (__nv_bfloat162*)(lo + i);
    ph[0] = __nv_bfloat162{h[0], h[1]};
    ph[1] = __nv_bfloat162{h[2], h[3]};
    pl[0] = __nv_bfloat162{l[0], l[1]};
    pl[1] = __nv_bfloat162{l[2], l[3]};
}

// =============================================================================
// bf16 3-term mma.sync GEMM (unchanged from R9 — proven, 1.4e-5)
// =============================================================================
#define BKC 32
#define AROWB 80
#define TILEB (128 * AROWB)
#define STAGEB (4 * TILEB)
#define GEMM_SMEM (2 * STAGEB)

template<int MODE>
__global__ __launch_bounds__(256, 1)
void gemm_bf16(const __nv_bfloat16* __restrict__ Ahi, const __nv_bfloat16* __restrict__ Alo,
               const __nv_bfloat16* __restrict__ Bhi, const __nv_bfloat16* __restrict__ Blo,
               const float* __restrict__ bias, float* __restrict__ C)
{
    extern __shared__ char smem[];
    const uint32_t smem_base = smem_u32(smem);
    const int tid  = threadIdx.x;
    const int lane = tid & 31;
    const int warp = tid >> 5;
    const int wm   = warp >> 2;
    const int wn   = warp & 3;
    const int rowBase = blockIdx.y * 128;
    const int colBase = blockIdx.x * 128;

    const __nv_bfloat16* srcs[4] = {
        Ahi + (size_t)rowBase * GK, Alo + (size_t)rowBase * GK,
        Bhi + (size_t)colBase * GK, Blo + (size_t)colBase * GK };

    const uint32_t aOff = (lane & 15) * AROWB + (lane >> 4) * 16;
    const uint32_t bOff = ((lane & 7) + ((lane >> 4) << 3)) * AROWB
                        + ((lane >> 3) & 1) * 16;

    float acc[4][4][4];
#pragma unroll
    for (int mt = 0; mt < 4; mt++)
#pragma unroll
        for (int nt = 0; nt < 4; nt++)
#pragma unroll
            for (int e = 0; e < 4; e++) acc[mt][nt][e] = 0.f;

    auto load_stage = [&](int kc, int stg) {
        const int kbase = kc * BKC;
        const uint32_t sbase = smem_base + stg * STAGEB;
#pragma unroll
        for (int i = 0; i < 8; i++) {
            const int task = tid + i * 256;
            const int tile = task >> 9;
            const int rem  = task & 511;
            const int r    = rem >> 2;
            const int ch   = rem & 3;
            const void* src = srcs[tile] + (size_t)r * GK + kbase + ch * 8;
            cp16(sbase + tile * TILEB + r * AROWB + ch * 16, src);
        }
    };

    auto compute_stage = [&](int stg) {
        const uint32_t sb  = smem_base + stg * STAGEB;
        const uint32_t sAh = sb;
        const uint32_t sAl = sb + TILEB;
        const uint32_t sBh = sb + 2 * TILEB;
        const uint32_t sBl = sb + 3 * TILEB;
#pragma unroll
        for (int ks = 0; ks < 2; ks++) {
            const uint32_t kb = ks * 32;
            uint32_t ah[4][4], al[4][4];
#pragma unroll
            for (int mt = 0; mt < 4; mt++) {
                const uint32_t ro = (wm * 64 + mt * 16) * AROWB + kb;
                ldsm4(ah[mt][0], ah[mt][1], ah[mt][2], ah[mt][3], sAh + ro + aOff);
                ldsm4(al[mt][0], al[mt][1], al[mt][2], al[mt][3], sAl + ro + aOff);
            }
            uint32_t bh[4][2], bl[4][2];
#pragma unroll
            for (int np = 0; np < 2; np++) {
                const uint32_t ro = (wn * 32 + np * 16) * AROWB + kb;
                ldsm4(bh[2*np][0], bh[2*np][1], bh[2*np+1][0], bh[2*np+1][1], sBh + ro + bOff);
                ldsm4(bl[2*np][0], bl[2*np][1], bl[2*np+1][0], bl[2*np+1][1], sBl + ro + bOff);
            }
#pragma unroll
            for (int mt = 0; mt < 4; mt++)
#pragma unroll
                for (int nt = 0; nt < 4; nt++) {
                    mma16816(acc[mt][nt], ah[mt][0], ah[mt][1], ah[mt][2], ah[mt][3],
                             bh[nt][0], bh[nt][1]);
                    mma16816(acc[mt][nt], ah[mt][0], ah[mt][1], ah[mt][2], ah[mt][3],
                             bl[nt][0], bl[nt][1]);
                    mma16816(acc[mt][nt], al[mt][0], al[mt][1], al[mt][2], al[mt][3],
                             bh[nt][0], bh[nt][1]);
                }
        }
    };

    const int NSTAGES = GK / BKC;
    load_stage(0, 0);
    cp_commit();

    for (int kt = 0; kt < NSTAGES; kt++) {
        if (kt + 1 < NSTAGES) {
            load_stage(kt + 1, (kt + 1) & 1);
            cp_commit();
            cp_wait<1>();
        } else {
            cp_wait<0>();
        }
        __syncthreads();
        compute_stage(kt & 1);
        __syncthreads();
    }

    const int g = lane >> 2;
    const int q = lane & 3;
#pragma unroll
    for (int mt = 0; mt < 4; mt++) {
        const int mBase = rowBase + wm * 64 + mt * 16 + g;
#pragma unroll
        for (int nt = 0; nt < 4; nt++) {
            const int n = colBase + wn * 32 + nt * 8 + 2 * q;
#pragma unroll
            for (int rr = 0; rr < 2; rr++) {
                const int m = mBase + rr * 8;
                const float c0 = acc[mt][nt][rr * 2 + 0];
                const float c1 = acc[mt][nt][rr * 2 + 1];
                if (MODE == 0) {
                    const int b = m >> 11, s = m & (SS - 1);
                    const int h = n >> 6,  hs = n & 63;
                    float2 v; v.x = c0; v.y = c1;
                    *(float2*)&C[(((size_t)(b * HH + h)) * SS + s) * HSZ + hs] = v;
                } else {
                    float2 bv = *(const float2*)&bias[n];
                    float2 v; v.x = c0 + bv.x; v.y = c1 + bv.y;
                    *(float2*)&C[(size_t)m * DD + n] = v;
                }
            }
        }
    }
}

// =============================================================================
// Causal flash attention, bf16 3-term mma.sync + poly-exp softmax.
// CTA: 128 q-rows x 1 head. 8 warps; warp = 16 rows x full 64-key tile.
// P register-resident. Writes chi/clo (bf16 hi/lo of context) directly.
// =============================================================================
#define FROWB 144                       // 64 bf16 = 128B + 16B pad
#define FQH 0
#define FQL (128 * FROWB)               // 18432
#define FKH (2 * 128 * FROWB)           // 36864
#define FKL (FKH + 64 * FROWB)
#define FVH (FKH + 2 * 64 * FROWB)
#define FVL (FVH + 64 * FROWB)
#define FLASH_SMEM (FKH + 4 * 64 * FROWB)   // 73728

__global__ __launch_bounds__(256, 2)
void flash_mma(const float* __restrict__ Q, const float* __restrict__ K,
               const float* __restrict__ V,
               __nv_bfloat16* __restrict__ chi, __nv_bfloat16* __restrict__ clo)
{
    extern __shared__ char fsm[];
    const uint32_t sb = smem_u32(fsm);
    const int tid  = threadIdx.x;
    const int lane = tid & 31;
    const int w    = tid >> 5;           // 0..7, warp owns q-rows w*16..+15
    const int g    = lane >> 2;
    const int q    = lane & 3;
    const int qt   = blockIdx.x;         // 128-row query tile
    const int bh   = blockIdx.y;

    const uint32_t aOff = (lane & 15) * FROWB + (lane >> 4) * 16;
    const uint32_t bOff = ((lane & 7) + ((lane >> 4) << 3)) * FROWB
                        + ((lane >> 3) & 1) * 16;

    // ---- stage Q (128x64) as hi/lo bf16 ----
    const float* Qb = Q + ((size_t)bh * SS + qt * 128) * HSZ;
    for (int i = tid; i < 128 * 32; i += 256) {
        const int r = i >> 5, c2 = i & 31;
        float2 v = *(const float2*)(Qb + r * 64 + 2 * c2);
        uint32_t h, l; split2(v.x, v.y, h, l);
        *(uint32_t*)(fsm + FQH + r * FROWB + c2 * 4) = h;
        *(uint32_t*)(fsm + FQL + r * FROWB + c2 * 4) = l;
    }

    float o[8][4];
    float m0 = -1e30f, m1 = -1e30f, l0 = 0.f, l1 = 0.f;
#pragma unroll
    for (int nt = 0; nt < 8; nt++)
#pragma unroll
        for (int e = 0; e < 4; e++) o[nt][e] = 0.f;

    const int ktmax = 2 * qt + 1;
    for (int kt = 0; kt <= ktmax; kt++) {
        const float* Kb = K + ((size_t)bh * SS + kt * 64) * HSZ;
        const float* Vb = V + ((size_t)bh * SS + kt * 64) * HSZ;

        __syncthreads();                 // prior tile compute done (also covers Q)
        for (int i = tid; i < 64 * 32; i += 256) {
            const int r = i >> 5, c2 = i & 31;
            float2 v = *(const float2*)(Kb + r * 64 + 2 * c2);
            uint32_t h, l; split2(v.x, v.y, h, l);
            *(uint32_t*)(fsm + FKH + r * FROWB + c2 * 4) = h;
            *(uint32_t*)(fsm + FKL + r * FROWB + c2 * 4) = l;
        }
        for (int i = tid; i < 64 * 32; i += 256) {
            const int d = i & 63, c2 = i >> 6;
            const float v0 = Vb[(2 * c2) * 64 + d];
            const float v1 = Vb[(2 * c2 + 1) * 64 + d];
            uint32_t h, l; split2(v0, v1, h, l);
            *(uint32_t*)(fsm + FVH + d * FROWB + c2 * 4) = h;
            *(uint32_t*)(fsm + FVL + d * FROWB + c2 * 4) = l;
        }
        __syncthreads();

        // ---- S = Q K^T (3-term bf16) ----
        float s[8][4];
#pragma unroll
        for (int nt = 0; nt < 8; nt++)
#pragma unroll
            for (int e = 0; e < 4; e++) s[nt][e] = 0.f;

#pragma unroll
        for (int ks = 0; ks < 4; ks++) {
            uint32_t qh[4], ql[4];
            const uint32_t aro = (w * 16) * FROWB + ks * 32 + aOff;
            ldsm4(qh[0], qh[1], qh[2], qh[3], sb + FQH + aro);
            ldsm4(ql[0], ql[1], ql[2], ql[3], sb + FQL + aro);
#pragma unroll
            for (int np = 0; np < 4; np++) {
                uint32_t kh[4], kl[4];
                const uint32_t bro = (np * 16) * FROWB + ks * 32 + bOff;
                ldsm4(kh[0], kh[1], kh[2], kh[3], sb + FKH + bro);
                ldsm4(kl[0], kl[1], kl[2], kl[3], sb + FKL + bro);
                mma16816(s[2*np],   qh[0], qh[1], qh[2], qh[3], kh[0], kh[1]);
                mma16816(s[2*np],   qh[0], qh[1], qh[2], qh[3], kl[0], kl[1]);
                mma16816(s[2*np],   ql[0], ql[1], ql[2], ql[3], kh[0], kh[1]);
                mma16816(s[2*np+1], qh[0], qh[1], qh[2], qh[3], kh[2], kh[3]);
                mma16816(s[2*np+1], qh[0], qh[1], qh[2], qh[3], kl[2], kl[3]);
                mma16816(s[2*np+1], ql[0], ql[1], ql[2], ql[3], kh[2], kh[3]);
            }
        }

        // ---- scale + causal mask ----
        const int rbase = qt * 128 + w * 16 + g;
        const bool needMask = (kt * 64 + 63) > (qt * 128 + w * 16);
#pragma unroll
        for (int nt = 0; nt < 8; nt++)
#pragma unroll
            for (int e = 0; e < 4; e++) {
                float v = s[nt][e] * 0.125f;
                if (needMask) {
                    const int row = rbase + ((e >> 1) << 3);
                    const int col = kt * 64 + nt * 8 + 2 * q + (e & 1);
                    if (col > row) v = -1e30f;
                }
                s[nt][e] = v;
            }

        // ---- online softmax (rows g / g+8; 4-lane q-group reductions) ----
        float rm0 = -1e30f, rm1 = -1e30f;
#pragma unroll
        for (int nt = 0; nt < 8; nt++) {
            rm0 = fmaxf(rm0, fmaxf(s[nt][0], s[nt][1]));
            rm1 = fmaxf(rm1, fmaxf(s[nt][2], s[nt][3]));
        }
        rm0 = fmaxf(rm0, __shfl_xor_sync(0xffffffffu, rm0, 1));
        rm0 = fmaxf(rm0, __shfl_xor_sync(0xffffffffu, rm0, 2));
        rm1 = fmaxf(rm1, __shfl_xor_sync(0xffffffffu, rm1, 1));
        rm1 = fmaxf(rm1, __shfl_xor_sync(0xffffffffu, rm1, 2));

        const float M0 = fmaxf(m0, rm0), M1 = fmaxf(m1, rm1);
        const float c0 = fexp(m0 - M0),  c1 = fexp(m1 - M1);
        m0 = M0; m1 = M1;

        float rs0 = 0.f, rs1 = 0.f;
#pragma unroll
        for (int nt = 0; nt < 8; nt++) {
            s[nt][0] = fexp(s[nt][0] - M0); rs0 += s[nt][0];
            s[nt][1] = fexp(s[nt][1] - M0); rs0 += s[nt][1];
            s[nt][2] = fexp(s[nt][2] - M1); rs1 += s[nt][2];
            s[nt][3] = fexp(s[nt][3] - M1); rs1 += s[nt][3];
        }
        rs0 += __shfl_xor_sync(0xffffffffu, rs0, 1);
        rs0 += __shfl_xor_sync(0xffffffffu, rs0, 2);
        rs1 += __shfl_xor_sync(0xffffffffu, rs1, 1);
        rs1 += __shfl_xor_sync(0xffffffffu, rs1, 2);
        l0 = l0 * c0 + rs0;
        l1 = l1 * c1 + rs1;

#pragma unroll
        for (int nt = 0; nt < 8; nt++) {
            o[nt][0] *= c0; o[nt][1] *= c0;
            o[nt][2] *= c1; o[nt][3] *= c1;
        }

        // ---- O += P V  (P register-resident hi/lo) ----
#pragma unroll
        for (int kc = 0; kc < 4; kc++) {
            uint32_t ph[4], pl[4];
            split2(s[2*kc][0],   s[2*kc][1],   ph[0], pl[0]);
            split2(s[2*kc][2],   s[2*kc][3],   ph[1], pl[1]);
            split2(s[2*kc+1][0], s[2*kc+1][1], ph[2], pl[2]);
            split2(s[2*kc+1][2], s[2*kc+1][3], ph[3], pl[3]);
#pragma unroll
            for (int np = 0; np < 4; np++) {
                uint32_t vh[4], vl[4];
                const uint32_t bro = (np * 16) * FROWB + kc * 32 + bOff;
                ldsm4(vh[0], vh[1], vh[2], vh[3], sb + FVH + bro);
                ldsm4(vl[0], vl[1], vl[2], vl[3], sb + FVL + bro);
                mma16816(o[2*np],   ph[0], ph[1], ph[2], ph[3], vh[0], vh[1]);
                mma16816(o[2*np],   ph[0], ph[1], ph[2], ph[3], vl[0], vl[1]);
                mma16816(o[2*np],   pl[0], pl[1], pl[2], pl[3], vh[0], vh[1]);
                mma16816(o[2*np+1], ph[0], ph[1], ph[2], ph[3], vh[2], vh[3]);
                mma16816(o[2*np+1], ph[0], ph[1], ph[2], ph[3], vl[2], vl[3]);
                mma16816(o[2*np+1], pl[0], pl[1], pl[2], pl[3], vh[2], vh[3]);
            }
        }
    }

    // ---- epilogue: normalize, write bf16 hi/lo context [b,s,d] ----
    const int b = bh >> 4, h = bh & 15;
    const int row0 = qt * 128 + w * 16 + g;
    const int row1 = row0 + 8;
    const float inv0 = 1.f / l0, inv1 = 1.f / l1;
#pragma unroll
    for (int nt = 0; nt < 8; nt++) {
        const int col = h * 64 + nt * 8 + 2 * q;
        uint32_t hh, ll;
        split2(o[nt][0] * inv0, o[nt][1] * inv0, hh, ll);
        const size_t off0 = ((size_t)(b * SS + row0)) * DD + col;
        *(uint32_t*)&chi[off0] = hh;
        *(uint32_t*)&clo[off0] = ll;
        split2(o[nt][2] * inv1, o[nt][3] * inv1, hh, ll);
        const size_t off1 = ((size_t)(b * SS + row1)) * DD + col;
        *(uint32_t*)&chi[off1] = hh;
        *(uint32_t*)&clo[off1] = ll;
    }
}

// =============================================================================
// launch
// =============================================================================
extern "C" void kernel_launch(void* const* d_in, const int* in_sizes, int n_in,
                              void* d_out, int out_size)
{
    const float* x  = (const float*)d_in[0];
    const float* Wk = (const float*)d_in[1];
    const float* Wq = (const float*)d_in[2];
    const float* Wv = (const float*)d_in[3];
    const float* Wo = (const float*)d_in[4];
    const float* bo = (const float*)d_in[5];
    float* out = (float*)d_out;

    float *Qh, *Kh, *Vh;
    __nv_bfloat16 *xhi, *xlo, *chi, *clo, *Whi, *Wlo;
    cudaGetSymbolAddress((void**)&Qh,  g_Qh);
    cudaGetSymbolAddress((void**)&Kh,  g_Kh);
    cudaGetSymbolAddress((void**)&Vh,  g_Vh);
    cudaGetSymbolAddress((void**)&xhi, g_xhi);
    cudaGetSymbolAddress((void**)&xlo, g_xlo);
    cudaGetSymbolAddress((void**)&chi, g_chi);
    cudaGetSymbolAddress((void**)&clo, g_clo);
    cudaGetSymbolAddress((void**)&Whi, g_Whi);
    cudaGetSymbolAddress((void**)&Wlo, g_Wlo);

    const size_t WSZ = (size_t)DD * DD;
    const int nX = MROWS * DD;
    const int nW = DD * DD;

    cudaFuncSetAttribute(gemm_bf16<0>, cudaFuncAttributeMaxDynamicSharedMemorySize, GEMM_SMEM);
    cudaFuncSetAttribute(gemm_bf16<1>, cudaFuncAttributeMaxDynamicSharedMemorySize, GEMM_SMEM);
    cudaFuncSetAttribute(flash_mma, cudaFuncAttributeMaxDynamicSharedMemorySize, FLASH_SMEM);

    // ---- hi/lo conversions (inputs only; ctx now produced by flash) ----
    convert_hilo<<<nX / 4 / 256, 256>>>(x,  xhi, xlo, nX);
    convert_hilo<<<nW / 4 / 256, 256>>>(Wq, Whi + 0 * WSZ, Wlo + 0 * WSZ, nW);
    convert_hilo<<<nW / 4 / 256, 256>>>(Wk, Whi + 1 * WSZ, Wlo + 1 * WSZ, nW);
    convert_hilo<<<nW / 4 / 256, 256>>>(Wv, Whi + 2 * WSZ, Wlo + 2 * WSZ, nW);
    convert_hilo<<<nW / 4 / 256, 256>>>(Wo, Whi + 3 * WSZ, Wlo + 3 * WSZ, nW);

    // ---- projections ----
    const dim3 gGemm(DD / 128, MROWS / 128);   // (8, 64)
    gemm_bf16<0><<<gGemm, 256, GEMM_SMEM>>>(xhi, xlo, Whi + 0 * WSZ, Wlo + 0 * WSZ, nullptr, Qh);
    gemm_bf16<0><<<gGemm, 256, GEMM_SMEM>>>(xhi, xlo, Whi + 1 * WSZ, Wlo + 1 * WSZ, nullptr, Kh);
    gemm_bf16<0><<<gGemm, 256, GEMM_SMEM>>>(xhi, xlo, Whi + 2 * WSZ, Wlo + 2 * WSZ, nullptr, Vh);

    // ---- attention (tensor-core flash) ----
    const dim3 gFlash(SS / 128, BHH);          // (16, 64)
    flash_mma<<<gFlash, 256, FLASH_SMEM>>>(Qh, Kh, Vh, chi, clo);

    // ---- output projection ----
    gemm_bf16<1><<<gGemm, 256, GEMM_SMEM>>>(chi, clo, Whi + 3 * WSZ, Wlo + 3 * WSZ, bo, out);
}

// round 16
// speedup vs baseline: 3.5058x; 1.1771x over previous
#include <cuda_runtime.h>
#include <cuda_bf16.h>
#include <cstdint>

// Problem constants
#define BB 4
#define SS 2048
#define DD 1024
#define HH 16
#define HSZ 64
#define BHH (BB*HH)       // 64
#define MROWS (BB*SS)     // 8192
#define GK DD             // 1024

// ---------------- scratch (static device globals; no allocation) -------------
__device__ __nv_bfloat16 g_Qhi[(size_t)BHH * SS * HSZ];   // [b,h,s,hs]
__device__ __nv_bfloat16 g_Qlo[(size_t)BHH * SS * HSZ];
__device__ __nv_bfloat16 g_Khi[(size_t)BHH * SS * HSZ];
__device__ __nv_bfloat16 g_Klo[(size_t)BHH * SS * HSZ];
__device__ __nv_bfloat16 g_Vthi[(size_t)BHH * HSZ * SS];  // [b,h,hs,s] (transposed)
__device__ __nv_bfloat16 g_Vtlo[(size_t)BHH * HSZ * SS];
__device__ __nv_bfloat16 g_xhi[(size_t)MROWS * DD];
__device__ __nv_bfloat16 g_xlo[(size_t)MROWS * DD];
__device__ __nv_bfloat16 g_chi[(size_t)MROWS * DD];
__device__ __nv_bfloat16 g_clo[(size_t)MROWS * DD];
__device__ __nv_bfloat16 g_Whi[4][(size_t)DD * DD];
__device__ __nv_bfloat16 g_Wlo[4][(size_t)DD * DD];

// =============================================================================
// helpers (arch-neutral: mma.sync / ldmatrix / cp.async — NO tcgen05)
// =============================================================================
__device__ __forceinline__ uint32_t smem_u32(const void* p) {
    uint32_t a;
    asm("{ .reg .u64 t; cvta.to.shared.u64 t, %1; cvt.u32.u64 %0, t; }"
        : "=r"(a) : "l"(p));
    return a;
}

__device__ __forceinline__ void cp16(uint32_t dst, const void* src) {
    asm volatile("cp.async.cg.shared.global [%0], [%1], 16;"
                 :: "r"(dst), "l"(src) : "memory");
}
__device__ __forceinline__ void cp_commit() {
    asm volatile("cp.async.commit_group;" ::: "memory");
}
template<int N>
__device__ __forceinline__ void cp_wait() {
    asm volatile("cp.async.wait_group %0;" :: "n"(N) : "memory");
}

__device__ __forceinline__ void ldsm4(uint32_t& r0, uint32_t& r1,
                                      uint32_t& r2, uint32_t& r3, uint32_t a) {
    asm volatile("ldmatrix.sync.aligned.m8n8.x4.shared.b16 {%0,%1,%2,%3}, [%4];"
                 : "=r"(r0), "=r"(r1), "=r"(r2), "=r"(r3) : "r"(a));
}

__device__ __forceinline__ void mma16816(float* c,
                                         uint32_t a0, uint32_t a1, uint32_t a2, uint32_t a3,
                                         uint32_t b0, uint32_t b1) {
    asm volatile(
        "mma.sync.aligned.m16n8k16.row.col.f32.bf16.bf16.f32 "
        "{%0,%1,%2,%3}, {%4,%5,%6,%7}, {%8,%9}, {%0,%1,%2,%3};"
        : "+f"(c[0]), "+f"(c[1]), "+f"(c[2]), "+f"(c[3])
        : "r"(a0), "r"(a1), "r"(a2), "r"(a3), "r"(b0), "r"(b1));
}

__device__ __forceinline__ void split2(float x, float y, uint32_t& h, uint32_t& l) {
    __nv_bfloat16 h0 = __float2bfloat16_rn(x);
    __nv_bfloat16 h1 = __float2bfloat16_rn(y);
    __nv_bfloat16 l0 = __float2bfloat16_rn(x - __bfloat162float(h0));
    __nv_bfloat16 l1 = __float2bfloat16_rn(y - __bfloat162float(h1));
    __nv_bfloat162 hh{h0, h1}, ll{l0, l1};
    h = *(uint32_t*)&hh;
    l = *(uint32_t*)&ll;
}

__device__ __forceinline__ uint32_t swz(uint32_t off) {       // SW128
    return off ^ ((off >> 3) & 0x70);
}

// fast exp on fma/alu pipes (no MUFU); ~2e-6 rel err
__device__ __forceinline__ float fexp(float x) {
    float z = fmaxf(x * 1.442695041f, -126.0f);
    float t = z + 12582912.0f;
    float n = t - 12582912.0f;
    float f = z - n;
    int   e = (__float_as_int(t) & 0x7FFFFF) - 0x400000;
    float p = 1.3333558e-3f;
    p = fmaf(p, f, 9.6181291e-3f);
    p = fmaf(p, f, 5.5504109e-2f);
    p = fmaf(p, f, 2.4022651e-1f);
    p = fmaf(p, f, 6.9314718e-1f);
    p = fmaf(p, f, 1.0f);
    return p * __int_as_float((e + 127) << 23);
}

// =============================================================================
// fp32 -> bf16 (hi, lo) split conversion
// =============================================================================
__global__ void convert_hilo(const float* __restrict__ s,
                             __nv_bfloat16* __restrict__ hi,
                             __nv_bfloat16* __restrict__ lo, int n)
{
    const int i = (blockIdx.x * blockDim.x + threadIdx.x) << 2;
    if (i >= n) return;
    float4 v = *(const float4*)(s + i);
    float f[4] = {v.x, v.y, v.z, v.w};
    __nv_bfloat16 h[4], l[4];
#pragma unroll
    for (int j = 0; j < 4; j++) {
        h[j] = __float2bfloat16_rn(f[j]);
        l[j] = __float2bfloat16_rn(f[j] - __bfloat162float(h[j]));
    }
    __nv_bfloat162* ph = (__nv_bfloat162*)(hi + i);
    __nv_bfloat162* pl = (__nv_bfloat162*)(lo + i);
    ph[0] = __nv_bfloat162{h[0], h[1]};
    ph[1] = __nv_bfloat162{h[2], h[3]};
    pl[0] = __nv_bfloat162{l[0], l[1]};
    pl[1] = __nv_bfloat162{l[2], l[3]};
}

// =============================================================================
// bf16 3-term mma.sync GEMM: C[8192,1024] = A[M,K]*W[N,K]^T
// 128x128 CTA tile, BK=32, 8 warps (warp 64x32), single-sync double buffer,
// __launch_bounds__(256,2) for 16 warps/SM.
// MODE 0: bf16 hi/lo out, head layout [b,h,s,hs]
// MODE 1: fp32 out row-major + bias
// MODE 2: bf16 hi/lo out, transposed head layout [b,h,hs,s]
// =============================================================================
#define BKC 32
#define AROWB 80
#define TILEB (128 * AROWB)
#define STAGEB (4 * TILEB)
#define GEMM_SMEM (2 * STAGEB)     // 81920

template<int MODE>
__global__ __launch_bounds__(256, 2)
void gemm_bf16(const __nv_bfloat16* __restrict__ Ahi, const __nv_bfloat16* __restrict__ Alo,
               const __nv_bfloat16* __restrict__ Bhi, const __nv_bfloat16* __restrict__ Blo,
               const float* __restrict__ bias, float* __restrict__ Cf,
               __nv_bfloat16* __restrict__ Chi, __nv_bfloat16* __restrict__ Clo)
{
    extern __shared__ char smem[];
    const uint32_t smem_base = smem_u32(smem);
    const int tid  = threadIdx.x;
    const int lane = tid & 31;
    const int warp = tid >> 5;
    const int wm   = warp >> 2;
    const int wn   = warp & 3;
    const int rowBase = blockIdx.y * 128;
    const int colBase = blockIdx.x * 128;

    const __nv_bfloat16* srcs[4] = {
        Ahi + (size_t)rowBase * GK, Alo + (size_t)rowBase * GK,
        Bhi + (size_t)colBase * GK, Blo + (size_t)colBase * GK };

    const uint32_t aOff = (lane & 15) * AROWB + (lane >> 4) * 16;
    const uint32_t bOff = ((lane & 7) + ((lane >> 4) << 3)) * AROWB
                        + ((lane >> 3) & 1) * 16;

    float acc[4][4][4];
#pragma unroll
    for (int mt = 0; mt < 4; mt++)
#pragma unroll
        for (int nt = 0; nt < 4; nt++)
#pragma unroll
            for (int e = 0; e < 4; e++) acc[mt][nt][e] = 0.f;

    auto load_stage = [&](int kc, int stg) {
        const int kbase = kc * BKC;
        const uint32_t sbase = smem_base + stg * STAGEB;
#pragma unroll
        for (int i = 0; i < 8; i++) {
            const int task = tid + i * 256;
            const int tile = task >> 9;
            const int rem  = task & 511;
            const int r    = rem >> 2;
            const int ch   = rem & 3;
            cp16(sbase + tile * TILEB + r * AROWB + ch * 16,
                 srcs[tile] + (size_t)r * GK + kbase + ch * 8);
        }
    };

    auto compute_stage = [&](int stg) {
        const uint32_t sb = smem_base + stg * STAGEB;
#pragma unroll
        for (int ks = 0; ks < 2; ks++) {
            const uint32_t kb = ks * 32;
            uint32_t bh[4][2], bl[4][2];
#pragma unroll
            for (int np = 0; np < 2; np++) {
                const uint32_t ro = (wn * 32 + np * 16) * AROWB + kb + bOff;
                ldsm4(bh[2*np][0], bh[2*np][1], bh[2*np+1][0], bh[2*np+1][1],
                      sb + 2 * TILEB + ro);
                ldsm4(bl[2*np][0], bl[2*np][1], bl[2*np+1][0], bl[2*np+1][1],
                      sb + 3 * TILEB + ro);
            }
#pragma unroll
            for (int mt = 0; mt < 4; mt++) {
                uint32_t ah[4], al[4];
                const uint32_t ro = (wm * 64 + mt * 16) * AROWB + kb + aOff;
                ldsm4(ah[0], ah[1], ah[2], ah[3], sb + ro);
                ldsm4(al[0], al[1], al[2], al[3], sb + TILEB + ro);
#pragma unroll
                for (int nt = 0; nt < 4; nt++) {
                    mma16816(acc[mt][nt], ah[0], ah[1], ah[2], ah[3], bh[nt][0], bh[nt][1]);
                    mma16816(acc[mt][nt], ah[0], ah[1], ah[2], ah[3], bl[nt][0], bl[nt][1]);
                    mma16816(acc[mt][nt], al[0], al[1], al[2], al[3], bh[nt][0], bh[nt][1]);
                }
            }
        }
    };

    const int NSTAGES = GK / BKC;      // 32
    load_stage(0, 0);
    cp_commit();

    for (int kt = 0; kt < NSTAGES; kt++) {
        cp_wait<0>();
        __syncthreads();
        if (kt + 1 < NSTAGES) {
            load_stage(kt + 1, (kt + 1) & 1);
            cp_commit();
        }
        compute_stage(kt & 1);
    }

    // ------------------------- epilogue -------------------------
    const int g = lane >> 2;
    const int q = lane & 3;
#pragma unroll
    for (int mt = 0; mt < 4; mt++) {
        const int mBase = rowBase + wm * 64 + mt * 16 + g;
#pragma unroll
        for (int nt = 0; nt < 4; nt++) {
            const int n = colBase + wn * 32 + nt * 8 + 2 * q;
#pragma unroll
            for (int rr = 0; rr < 2; rr++) {
                const int m = mBase + rr * 8;
                const float c0 = acc[mt][nt][rr * 2 + 0];
                const float c1 = acc[mt][nt][rr * 2 + 1];
                const int b = m >> 11, s = m & (SS - 1);
                const int h = n >> 6,  hs = n & 63;
                if (MODE == 0) {
                    uint32_t hh, ll; split2(c0, c1, hh, ll);
                    const size_t off = (((size_t)(b * HH + h)) * SS + s) * HSZ + hs;
                    *(uint32_t*)&Chi[off] = hh;
                    *(uint32_t*)&Clo[off] = ll;
                } else if (MODE == 2) {
                    // transposed: [b,h,hs,s]
                    __nv_bfloat16 h0 = __float2bfloat16_rn(c0);
                    __nv_bfloat16 h1 = __float2bfloat16_rn(c1);
                    __nv_bfloat16 l0 = __float2bfloat16_rn(c0 - __bfloat162float(h0));
                    __nv_bfloat16 l1 = __float2bfloat16_rn(c1 - __bfloat162float(h1));
                    const size_t base = (((size_t)(b * HH + h)) * HSZ + hs) * SS + s;
                    Chi[base] = h0;  Chi[base + SS] = h1;
                    Clo[base] = l0;  Clo[base + SS] = l1;
                } else {
                    float2 bv = *(const float2*)&bias[n];
                    float2 v; v.x = c0 + bv.x; v.y = c1 + bv.y;
                    *(float2*)&Cf[(size_t)m * DD + n] = v;
                }
            }
        }
    }
}

// =============================================================================
// Causal flash attention: cp.async swizzled staging of prestored bf16 hi/lo,
// double-buffered K/V stages, one barrier per tile, bf16 3-term mma.sync.
// CTA: 128 q-rows x 1 head; 8 warps; warp = 16 rows x full 64-key tile.
// =============================================================================
#define SQH 0
#define SQL 16384
#define FSTG 32768                  // stage base
#define STGB 32768                  // per stage: KH,KL,VH,VL each 8192
#define FLASH_SMEM (FSTG + 2 * STGB)  // 98304

__global__ __launch_bounds__(256, 2)
void flash_mma(const __nv_bfloat16* __restrict__ Qhi, const __nv_bfloat16* __restrict__ Qlo,
               const __nv_bfloat16* __restrict__ Khi, const __nv_bfloat16* __restrict__ Klo,
               const __nv_bfloat16* __restrict__ Vthi, const __nv_bfloat16* __restrict__ Vtlo,
               __nv_bfloat16* __restrict__ chi, __nv_bfloat16* __restrict__ clo)
{
    extern __shared__ char fsm[];
    const uint32_t sb = smem_u32(fsm);
    const int tid  = threadIdx.x;
    const int lane = tid & 31;
    const int w    = tid >> 5;
    const int g    = lane >> 2;
    const int q    = lane & 3;
    const int qt   = blockIdx.x;
    const int bh   = blockIdx.y;

    // ldsm logical coordinates (swizzle applied per-access)
    const uint32_t aRow = (lane & 15);
    const uint32_t aCol = (lane >> 4) * 16;
    const uint32_t bRow = (lane & 7) + ((lane >> 4) << 3);
    const uint32_t bCol = ((lane >> 3) & 1) * 16;

    // ---- prologue: stage Q (128 rows) + KV stage 0 ----
    {
        const __nv_bfloat16* qh = Qhi + ((size_t)bh * SS + qt * 128) * HSZ;
        const __nv_bfloat16* ql = Qlo + ((size_t)bh * SS + qt * 128) * HSZ;
        for (int i = tid; i < 128 * 8; i += 256) {
            const int r = i >> 3, ch = i & 7;
            const uint32_t off = swz(r * 128 + ch * 16);
            cp16(sb + SQH + off, qh + r * 64 + ch * 8);
            cp16(sb + SQL + off, ql + r * 64 + ch * 8);
        }
    }

    auto load_kv = [&](int kt, int stg) {
        const uint32_t st = sb + FSTG + stg * STGB;
        const __nv_bfloat16* kh = Khi + ((size_t)bh * SS + kt * 64) * HSZ;
        const __nv_bfloat16* kl = Klo + ((size_t)bh * SS + kt * 64) * HSZ;
        const __nv_bfloat16* vh = Vthi + (size_t)bh * HSZ * SS + kt * 64;
        const __nv_bfloat16* vl = Vtlo + (size_t)bh * HSZ * SS + kt * 64;
        for (int i = tid; i < 64 * 8; i += 256) {
            const int r = i >> 3, ch = i & 7;
            const uint32_t off = swz(r * 128 + ch * 16);
            cp16(st + off,             kh + r * 64 + ch * 8);
            cp16(st + 8192 + off,      kl + r * 64 + ch * 8);
            cp16(st + 16384 + off,     vh + (size_t)r * SS + ch * 8);
            cp16(st + 24576 + off,     vl + (size_t)r * SS + ch * 8);
        }
    };

    load_kv(0, 0);
    cp_commit();

    float o[8][4];
    float m0 = -1e30f, m1 = -1e30f, l0 = 0.f, l1 = 0.f;
#pragma unroll
    for (int nt = 0; nt < 8; nt++)
#pragma unroll
        for (int e = 0; e < 4; e++) o[nt][e] = 0.f;

    const int ktmax = 2 * qt + 1;
    for (int kt = 0; kt <= ktmax; kt++) {
        cp_wait<0>();
        __syncthreads();
        if (kt + 1 <= ktmax) {
            load_kv(kt + 1, (kt + 1) & 1);
            cp_commit();
        }
        const uint32_t st = sb + FSTG + (kt & 1) * STGB;

        // ---- S = Q K^T (3-term bf16) ----
        float s[8][4];
#pragma unroll
        for (int nt = 0; nt < 8; nt++)
#pragma unroll
            for (int e = 0; e < 4; e++) s[nt][e] = 0.f;

#pragma unroll
        for (int ks = 0; ks < 4; ks++) {
            uint32_t qh[4], ql[4];
            const uint32_t qoff = swz((w * 16 + aRow) * 128 + ks * 32 + aCol);
            ldsm4(qh[0], qh[1], qh[2], qh[3], sb + SQH + qoff);
            ldsm4(ql[0], ql[1], ql[2], ql[3], sb + SQL + qoff);
#pragma unroll
            for (int np = 0; np < 4; np++) {
                uint32_t kh[4], kl[4];
                const uint32_t koff = swz((np * 16 + bRow) * 128 + ks * 32 + bCol);
                ldsm4(kh[0], kh[1], kh[2], kh[3], st + koff);
                ldsm4(kl[0], kl[1], kl[2], kl[3], st + 8192 + koff);
                mma16816(s[2*np],   qh[0], qh[1], qh[2], qh[3], kh[0], kh[1]);
                mma16816(s[2*np],   qh[0], qh[1], qh[2], qh[3], kl[0], kl[1]);
                mma16816(s[2*np],   ql[0], ql[1], ql[2], ql[3], kh[0], kh[1]);
                mma16816(s[2*np+1], qh[0], qh[1], qh[2], qh[3], kh[2], kh[3]);
                mma16816(s[2*np+1], qh[0], qh[1], qh[2], qh[3], kl[2], kl[3]);
                mma16816(s[2*np+1], ql[0], ql[1], ql[2], ql[3], kh[2], kh[3]);
            }
        }

        // ---- scale + causal mask ----
        const int rbase = qt * 128 + w * 16 + g;
        const bool needMask = (kt * 64 + 63) > (qt * 128 + w * 16);
#pragma unroll
        for (int nt = 0; nt < 8; nt++)
#pragma unroll
            for (int e = 0; e < 4; e++) {
                float v = s[nt][e] * 0.125f;
                if (needMask) {
                    const int row = rbase + ((e >> 1) << 3);
                    const int col = kt * 64 + nt * 8 + 2 * q + (e & 1);
                    if (col > row) v = -1e30f;
                }
                s[nt][e] = v;
            }

        // ---- online softmax ----
        float rm0 = -1e30f, rm1 = -1e30f;
#pragma unroll
        for (int nt = 0; nt < 8; nt++) {
            rm0 = fmaxf(rm0, fmaxf(s[nt][0], s[nt][1]));
            rm1 = fmaxf(rm1, fmaxf(s[nt][2], s[nt][3]));
        }
        rm0 = fmaxf(rm0, __shfl_xor_sync(0xffffffffu, rm0, 1));
        rm0 = fmaxf(rm0, __shfl_xor_sync(0xffffffffu, rm0, 2));
        rm1 = fmaxf(rm1, __shfl_xor_sync(0xffffffffu, rm1, 1));
        rm1 = fmaxf(rm1, __shfl_xor_sync(0xffffffffu, rm1, 2));

        const float M0 = fmaxf(m0, rm0), M1 = fmaxf(m1, rm1);
        const float c0 = fexp(m0 - M0),  c1 = fexp(m1 - M1);
        m0 = M0; m1 = M1;

        float rs0 = 0.f, rs1 = 0.f;
#pragma unroll
        for (int nt = 0; nt < 8; nt++) {
            s[nt][0] = fexp(s[nt][0] - M0); rs0 += s[nt][0];
            s[nt][1] = fexp(s[nt][1] - M0); rs0 += s[nt][1];
            s[nt][2] = fexp(s[nt][2] - M1); rs1 += s[nt][2];
            s[nt][3] = fexp(s[nt][3] - M1); rs1 += s[nt][3];
        }
        rs0 += __shfl_xor_sync(0xffffffffu, rs0, 1);
        rs0 += __shfl_xor_sync(0xffffffffu, rs0, 2);
        rs1 += __shfl_xor_sync(0xffffffffu, rs1, 1);
        rs1 += __shfl_xor_sync(0xffffffffu, rs1, 2);
        l0 = l0 * c0 + rs0;
        l1 = l1 * c1 + rs1;

#pragma unroll
        for (int nt = 0; nt < 8; nt++) {
            o[nt][0] *= c0; o[nt][1] *= c0;
            o[nt][2] *= c1; o[nt][3] *= c1;
        }

        // ---- O += P V (P register-resident hi/lo; V^T tile rows = d) ----
#pragma unroll
        for (int kc = 0; kc < 4; kc++) {
            uint32_t ph[4], pl[4];
            split2(s[2*kc][0],   s[2*kc][1],   ph[0], pl[0]);
            split2(s[2*kc][2],   s[2*kc][3],   ph[1], pl[1]);
            split2(s[2*kc+1][0], s[2*kc+1][1], ph[2], pl[2]);
            split2(s[2*kc+1][2], s[2*kc+1][3], ph[3], pl[3]);
#pragma unroll
            for (int np = 0; np < 4; np++) {
                uint32_t vh[4], vl[4];
                const uint32_t voff = swz((np * 16 + bRow) * 128 + kc * 32 + bCol);
                ldsm4(vh[0], vh[1], vh[2], vh[3], st + 16384 + voff);
                ldsm4(vl[0], vl[1], vl[2], vl[3], st + 24576 + voff);
                mma16816(o[2*np],   ph[0], ph[1], ph[2], ph[3], vh[0], vh[1]);
                mma16816(o[2*np],   ph[0], ph[1], ph[2], ph[3], vl[0], vl[1]);
                mma16816(o[2*np],   pl[0], pl[1], pl[2], pl[3], vh[0], vh[1]);
                mma16816(o[2*np+1], ph[0], ph[1], ph[2], ph[3], vh[2], vh[3]);
                mma16816(o[2*np+1], ph[0], ph[1], ph[2], ph[3], vl[2], vl[3]);
                mma16816(o[2*np+1], pl[0], pl[1], pl[2], pl[3], vh[2], vh[3]);
            }
        }
        __syncthreads();    // all warps done with this stage before its reuse
    }

    // ---- epilogue: normalize, write bf16 hi/lo context [b,s,d] ----
    const int b = bh >> 4, h = bh & 15;
    const int row0 = qt * 128 + w * 16 + g;
    const int row1 = row0 + 8;
    const float inv0 = 1.f / l0, inv1 = 1.f / l1;
#pragma unroll
    for (int nt = 0; nt < 8; nt++) {
        const int col = h * 64 + nt * 8 + 2 * q;
        uint32_t hh, ll;
        split2(o[nt][0] * inv0, o[nt][1] * inv0, hh, ll);
        const size_t off0 = ((size_t)(b * SS + row0)) * DD + col;
        *(uint32_t*)&chi[off0] = hh;
        *(uint32_t*)&clo[off0] = ll;
        split2(o[nt][2] * inv1, o[nt][3] * inv1, hh, ll);
        const size_t off1 = ((size_t)(b * SS + row1)) * DD + col;
        *(uint32_t*)&chi[off1] = hh;
        *(uint32_t*)&clo[off1] = ll;
    }
}

// =============================================================================
// launch
// =============================================================================
extern "C" void kernel_launch(void* const* d_in, const int* in_sizes, int n_in,
                              void* d_out, int out_size)
{
    const float* x  = (const float*)d_in[0];
    const float* Wk = (const float*)d_in[1];
    const float* Wq = (const float*)d_in[2];
    const float* Wv = (const float*)d_in[3];
    const float* Wo = (const float*)d_in[4];
    const float* bo = (const float*)d_in[5];
    float* out = (float*)d_out;

    __nv_bfloat16 *Qhi, *Qlo, *Khi, *Klo, *Vthi, *Vtlo;
    __nv_bfloat16 *xhi, *xlo, *chi, *clo, *Whi, *Wlo;
    cudaGetSymbolAddress((void**)&Qhi,  g_Qhi);
    cudaGetSymbolAddress((void**)&Qlo,  g_Qlo);
    cudaGetSymbolAddress((void**)&Khi,  g_Khi);
    cudaGetSymbolAddress((void**)&Klo,  g_Klo);
    cudaGetSymbolAddress((void**)&Vthi, g_Vthi);
    cudaGetSymbolAddress((void**)&Vtlo, g_Vtlo);
    cudaGetSymbolAddress((void**)&xhi,  g_xhi);
    cudaGetSymbolAddress((void**)&xlo,  g_xlo);
    cudaGetSymbolAddress((void**)&chi,  g_chi);
    cudaGetSymbolAddress((void**)&clo,  g_clo);
    cudaGetSymbolAddress((void**)&Whi,  g_Whi);
    cudaGetSymbolAddress((void**)&Wlo,  g_Wlo);

    const size_t WSZ = (size_t)DD * DD;
    const int nX = MROWS * DD;
    const int nW = DD * DD;

    cudaFuncSetAttribute(gemm_bf16<0>, cudaFuncAttributeMaxDynamicSharedMemorySize, GEMM_SMEM);
    cudaFuncSetAttribute(gemm_bf16<1>, cudaFuncAttributeMaxDynamicSharedMemorySize, GEMM_SMEM);
    cudaFuncSetAttribute(gemm_bf16<2>, cudaFuncAttributeMaxDynamicSharedMemorySize, GEMM_SMEM);
    cudaFuncSetAttribute(flash_mma, cudaFuncAttributeMaxDynamicSharedMemorySize, FLASH_SMEM);

    // ---- hi/lo conversions ----
    convert_hilo<<<nX / 4 / 256, 256>>>(x,  xhi, xlo, nX);
    convert_hilo<<<nW / 4 / 256, 256>>>(Wq, Whi + 0 * WSZ, Wlo + 0 * WSZ, nW);
    convert_hilo<<<nW / 4 / 256, 256>>>(Wk, Whi + 1 * WSZ, Wlo + 1 * WSZ, nW);
    convert_hilo<<<nW / 4 / 256, 256>>>(Wv, Whi + 2 * WSZ, Wlo + 2 * WSZ, nW);
    convert_hilo<<<nW / 4 / 256, 256>>>(Wo, Whi + 3 * WSZ, Wlo + 3 * WSZ, nW);

    // ---- projections (write bf16 hi/lo directly; V transposed) ----
    const dim3 gGemm(DD / 128, MROWS / 128);   // (8, 64)
    gemm_bf16<0><<<gGemm, 256, GEMM_SMEM>>>(xhi, xlo, Whi + 0 * WSZ, Wlo + 0 * WSZ,
                                            nullptr, nullptr, Qhi, Qlo);
    gemm_bf16<0><<<gGemm, 256, GEMM_SMEM>>>(xhi, xlo, Whi + 1 * WSZ, Wlo + 1 * WSZ,
                                            nullptr, nullptr, Khi, Klo);
    gemm_bf16<2><<<gGemm, 256, GEMM_SMEM>>>(xhi, xlo, Whi + 2 * WSZ, Wlo + 2 * WSZ,
                                            nullptr, nullptr, Vthi, Vtlo);

    // ---- attention ----
    const dim3 gFlash(SS / 128, BHH);          // (16, 64)
    flash_mma<<<gFlash, 256, FLASH_SMEM>>>(Qhi, Qlo, Khi, Klo, Vthi, Vtlo, chi, clo);

    // ---- output projection ----
    gemm_bf16<1><<<gGemm, 256, GEMM_SMEM>>>(chi, clo, Whi + 3 * WSZ, Wlo + 3 * WSZ,
                                            bo, out, nullptr, nullptr);
}